// round 1
// baseline (speedup 1.0000x reference)
#include <cuda_runtime.h>
#include <cuda_bf16.h>

#ifndef CNT_C
#define CNT_C 2048
#endif
#define STEPS_PER_THREAD 8
#define THREADS 256

struct Quat { float w, x, y, z; };

__device__ __forceinline__ Quat qmul(const Quat a, const Quat b) {
    Quat o;
    o.w = a.w * b.w - a.x * b.x - a.y * b.y - a.z * b.z;
    o.x = a.w * b.x + a.x * b.w + a.y * b.z - a.z * b.y;
    o.y = a.w * b.y - a.x * b.z + a.y * b.w + a.z * b.x;
    o.z = a.w * b.z + a.x * b.y - a.y * b.x + a.z * b.w;
    return o;
}

__global__ __launch_bounds__(THREADS)
void tinygc2l_kernel(const float* __restrict__ ts,
                     const float* __restrict__ gyro,
                     const float* __restrict__ q0g,
                     const float* __restrict__ W1,
                     const float* __restrict__ B1,
                     const float* __restrict__ A1,
                     const float* __restrict__ W2,
                     const float* __restrict__ B2,
                     const float* __restrict__ A2,
                     float* __restrict__ out,
                     int CNT)
{
    __shared__ float s_g[CNT_C * 3];   // 24 KB
    __shared__ float s_t[CNT_C];       //  8 KB
    __shared__ float4 s_wq[THREADS / 32];

    const int b   = blockIdx.x;
    const int tid = threadIdx.x;
    const int lane = tid & 31;
    const int wid  = tid >> 5;

    // ---- cooperative coalesced stage of this row into smem ----
    {
        const float4* gsrc = reinterpret_cast<const float4*>(gyro + (size_t)b * CNT * 3);
        float4* gdst = reinterpret_cast<float4*>(s_g);
        const int n4g = (CNT * 3) / 4;            // 1536
        #pragma unroll
        for (int i = tid; i < n4g; i += THREADS) gdst[i] = gsrc[i];

        const float4* tsrc = reinterpret_cast<const float4*>(ts + (size_t)b * CNT);
        float4* tdst = reinterpret_cast<float4*>(s_t);
        const int n4t = CNT / 4;                   // 512
        #pragma unroll
        for (int i = tid; i < n4t; i += THREADS) tdst[i] = tsrc[i];
    }

    // ---- tiny-net weights into registers (uniform broadcast loads) ----
    float w1[9], w2[9], bb1[3], bb2[3];
    #pragma unroll
    for (int i = 0; i < 9; i++) { w1[i] = W1[i]; w2[i] = W2[i]; }
    #pragma unroll
    for (int i = 0; i < 3; i++) { bb1[i] = B1[i]; bb2[i] = B2[i]; }
    const float a1 = A1[0];
    const float a2 = A2[0];

    __syncthreads();

    // ---- g(t) evaluator from smem gyro ----
    auto g_eval = [&](int t, float& gx, float& gy, float& gz) {
        const float ix = s_g[3 * t + 0];
        const float iy = s_g[3 * t + 1];
        const float iz = s_g[3 * t + 2];
        float h0 = fmaf(w1[0], ix, fmaf(w1[1], iy, fmaf(w1[2], iz, bb1[0])));
        float h1 = fmaf(w1[3], ix, fmaf(w1[4], iy, fmaf(w1[5], iz, bb1[1])));
        float h2 = fmaf(w1[6], ix, fmaf(w1[7], iy, fmaf(w1[8], iz, bb1[2])));
        h0 = (h0 >= 0.f) ? h0 : a1 * h0;
        h1 = (h1 >= 0.f) ? h1 : a1 * h1;
        h2 = (h2 >= 0.f) ? h2 : a1 * h2;
        float g0 = fmaf(w2[0], h0, fmaf(w2[1], h1, fmaf(w2[2], h2, bb2[0])));
        float g1 = fmaf(w2[3], h0, fmaf(w2[4], h1, fmaf(w2[5], h2, bb2[1])));
        float g2 = fmaf(w2[6], h0, fmaf(w2[7], h1, fmaf(w2[8], h2, bb2[2])));
        g0 = (g0 >= 0.f) ? g0 : a2 * g0;
        g1 = (g1 >= 0.f) ? g1 : a2 * g1;
        g2 = (g2 >= 0.f) ? g2 : a2 * g2;
        gx = g0 + ix; gy = g1 + iy; gz = g2 + iz;
    };

    // ---- per-thread ordered product over contiguous steps [t0, t1) ----
    const int t0 = tid * STEPS_PER_THREAD;
    const int t1 = min(t0 + STEPS_PER_THREAD, CNT - 1);

    Quat p; p.w = 1.f; p.x = 0.f; p.y = 0.f; p.z = 0.f;
    if (t0 < t1) {
        float gpx, gpy, gpz;
        g_eval(t0, gpx, gpy, gpz);
        float tprev = s_t[t0];
        #pragma unroll
        for (int t = t0; t < t1; ++t) {
            float gcx, gcy, gcz;
            g_eval(t + 1, gcx, gcy, gcz);
            const float tcur = s_t[t + 1];
            const float s = 0.25f * (tcur - tprev);
            Quat dq;
            dq.w = 1.f;
            dq.x = (gpx + gcx) * s;
            dq.y = (gpy + gcy) * s;
            dq.z = (gpz + gcz) * s;
            p = qmul(p, dq);
            gpx = gcx; gpy = gcy; gpz = gcz; tprev = tcur;
        }
        // normalize partial product (prevents f32 overflow in the tree)
        const float n2 = p.w * p.w + p.x * p.x + p.y * p.y + p.z * p.z;
        const float inv = rsqrtf(fmaxf(n2, 1e-24f));
        p.w *= inv; p.x *= inv; p.y *= inv; p.z *= inv;
    }

    // ---- ordered warp tree reduction: lane i holds product of [i, i+2^k) ----
    #pragma unroll
    for (int off = 1; off < 32; off <<= 1) {
        Quat q;
        q.w = __shfl_down_sync(0xffffffffu, p.w, off);
        q.x = __shfl_down_sync(0xffffffffu, p.x, off);
        q.y = __shfl_down_sync(0xffffffffu, p.y, off);
        q.z = __shfl_down_sync(0xffffffffu, p.z, off);
        if (lane + off < 32) p = qmul(p, q);
    }
    if (lane == 0) s_wq[wid] = make_float4(p.w, p.x, p.y, p.z);
    __syncthreads();

    // ---- warp 0: ordered reduce of the 8 warp products, finalize ----
    if (wid == 0) {
        Quat r; r.w = 1.f; r.x = 0.f; r.y = 0.f; r.z = 0.f;
        if (lane < THREADS / 32) {
            float4 v = s_wq[lane];
            r.w = v.x; r.x = v.y; r.y = v.z; r.z = v.w;
        }
        #pragma unroll
        for (int off = 1; off < THREADS / 32; off <<= 1) {
            Quat q;
            q.w = __shfl_down_sync(0xffffffffu, r.w, off);
            q.x = __shfl_down_sync(0xffffffffu, r.x, off);
            q.y = __shfl_down_sync(0xffffffffu, r.y, off);
            q.z = __shfl_down_sync(0xffffffffu, r.z, off);
            if (lane + off < THREADS / 32) r = qmul(r, q);
        }
        if (lane == 0) {
            Quat q0;
            const float* qp = q0g + (size_t)b * 4;
            q0.w = qp[0]; q0.x = qp[1]; q0.y = qp[2]; q0.z = qp[3];
            Quat f = qmul(q0, r);
            const float n = sqrtf(f.w * f.w + f.x * f.x + f.y * f.y + f.z * f.z);
            const float inv = 1.0f / fmaxf(n, 1e-12f);
            float* op = out + (size_t)b * 4;
            op[0] = f.w * inv;
            op[1] = f.x * inv;
            op[2] = f.y * inv;
            op[3] = f.z * inv;
        }
    }
}

extern "C" void kernel_launch(void* const* d_in, const int* in_sizes, int n_in,
                              void* d_out, int out_size) {
    const float* ts   = (const float*)d_in[0];
    const float* gyro = (const float*)d_in[1];
    const float* q0   = (const float*)d_in[2];
    const float* W1   = (const float*)d_in[3];
    const float* b1   = (const float*)d_in[4];
    const float* a1   = (const float*)d_in[5];
    const float* W2   = (const float*)d_in[6];
    const float* b2   = (const float*)d_in[7];
    const float* a2   = (const float*)d_in[8];
    float* out = (float*)d_out;

    const int B   = in_sizes[2] / 4;         // start_quat is (B,4)
    const int CNT = in_sizes[0] / B;         // timestamps are (B,CNT); expect 2048

    tinygc2l_kernel<<<B, THREADS>>>(ts, gyro, q0, W1, b1, a1, W2, b2, a2, out, CNT);
}

// round 2
// speedup vs baseline: 1.9708x; 1.9708x over previous
#include <cuda_runtime.h>
#include <cuda_bf16.h>

#define STEPS_PER_THREAD 8
#define THREADS 256

struct Quat { float w, x, y, z; };

__device__ __forceinline__ Quat qmul(const Quat a, const Quat b) {
    Quat o;
    o.w = a.w * b.w - a.x * b.x - a.y * b.y - a.z * b.z;
    o.x = a.w * b.x + a.x * b.w + a.y * b.z - a.z * b.y;
    o.y = a.w * b.y - a.x * b.z + a.y * b.w + a.z * b.x;
    o.z = a.w * b.z + a.x * b.y - a.y * b.x + a.z * b.w;
    return o;
}

__global__ __launch_bounds__(THREADS)
void tinygc2l_kernel(const float* __restrict__ ts,
                     const float* __restrict__ gyro,
                     const float* __restrict__ q0g,
                     const float* __restrict__ W1,
                     const float* __restrict__ B1,
                     const float* __restrict__ A1,
                     const float* __restrict__ W2,
                     const float* __restrict__ B2,
                     const float* __restrict__ A2,
                     float* __restrict__ out,
                     int CNT)
{
    __shared__ float4 s_wq[THREADS / 32];

    const int b    = blockIdx.x;
    const int tid  = threadIdx.x;
    const int lane = tid & 31;
    const int wid  = tid >> 5;
    const int t0   = tid * STEPS_PER_THREAD;

    // ---- direct vectorized global->register load of this thread's tile ----
    // 8 gyro points (24 floats = 6 float4) + 8 timestamps (2 float4), all
    // 16B-aligned (per-thread offsets are multiples of 96B / 32B).
    float gf[27];           // points t0..t0+8 (point 8 loaded separately)
    float tf[9];
    {
        const float4* gsrc = reinterpret_cast<const float4*>(
            gyro + (size_t)b * CNT * 3 + (size_t)t0 * 3);
        #pragma unroll
        for (int i = 0; i < 6; i++) {
            float4 v = gsrc[i];
            gf[4 * i + 0] = v.x; gf[4 * i + 1] = v.y;
            gf[4 * i + 2] = v.z; gf[4 * i + 3] = v.w;
        }
        const float4* tsrc = reinterpret_cast<const float4*>(
            ts + (size_t)b * CNT + t0);
        #pragma unroll
        for (int i = 0; i < 2; i++) {
            float4 v = tsrc[i];
            tf[4 * i + 0] = v.x; tf[4 * i + 1] = v.y;
            tf[4 * i + 2] = v.z; tf[4 * i + 3] = v.w;
        }
        // boundary point t0+8 (L1 hit: same lines the neighbor thread loaded)
        const bool have8 = (t0 + 8 <= CNT - 1);
        const float* gp8 = gyro + (size_t)b * CNT * 3 + (size_t)(t0 + 8) * 3;
        gf[24] = have8 ? gp8[0] : 0.f;
        gf[25] = have8 ? gp8[1] : 0.f;
        gf[26] = have8 ? gp8[2] : 0.f;
        tf[8]  = have8 ? ts[(size_t)b * CNT + t0 + 8] : 0.f;
    }

    // ---- tiny-net weights into registers ----
    float w1[9], w2[9], bb1[3], bb2[3];
    #pragma unroll
    for (int i = 0; i < 9; i++) { w1[i] = __ldg(W1 + i); w2[i] = __ldg(W2 + i); }
    #pragma unroll
    for (int i = 0; i < 3; i++) { bb1[i] = __ldg(B1 + i); bb2[i] = __ldg(B2 + i); }
    const float a1 = __ldg(A1);
    const float a2 = __ldg(A2);

    // ---- tiny-net on all 9 points (in place over gf) ----
    #pragma unroll
    for (int i = 0; i < 9; i++) {
        const float ix = gf[3 * i + 0];
        const float iy = gf[3 * i + 1];
        const float iz = gf[3 * i + 2];
        float h0 = fmaf(w1[0], ix, fmaf(w1[1], iy, fmaf(w1[2], iz, bb1[0])));
        float h1 = fmaf(w1[3], ix, fmaf(w1[4], iy, fmaf(w1[5], iz, bb1[1])));
        float h2 = fmaf(w1[6], ix, fmaf(w1[7], iy, fmaf(w1[8], iz, bb1[2])));
        h0 = (h0 >= 0.f) ? h0 : a1 * h0;
        h1 = (h1 >= 0.f) ? h1 : a1 * h1;
        h2 = (h2 >= 0.f) ? h2 : a1 * h2;
        float g0 = fmaf(w2[0], h0, fmaf(w2[1], h1, fmaf(w2[2], h2, bb2[0])));
        float g1 = fmaf(w2[3], h0, fmaf(w2[4], h1, fmaf(w2[5], h2, bb2[1])));
        float g2 = fmaf(w2[6], h0, fmaf(w2[7], h1, fmaf(w2[8], h2, bb2[2])));
        g0 = (g0 >= 0.f) ? g0 : a2 * g0;
        g1 = (g1 >= 0.f) ? g1 : a2 * g1;
        g2 = (g2 >= 0.f) ? g2 : a2 * g2;
        gf[3 * i + 0] = g0 + ix;
        gf[3 * i + 1] = g1 + iy;
        gf[3 * i + 2] = g2 + iz;
    }

    // ---- ordered product of this thread's steps ----
    const int nsteps = max(0, min(STEPS_PER_THREAD, (CNT - 1) - t0));
    Quat p; p.w = 1.f; p.x = 0.f; p.y = 0.f; p.z = 0.f;
    #pragma unroll
    for (int i = 0; i < STEPS_PER_THREAD; i++) {
        if (i < nsteps) {
            const float s = 0.25f * (tf[i + 1] - tf[i]);
            Quat dq;
            dq.w = 1.f;
            dq.x = (gf[3 * i + 0] + gf[3 * i + 3]) * s;
            dq.y = (gf[3 * i + 1] + gf[3 * i + 4]) * s;
            dq.z = (gf[3 * i + 2] + gf[3 * i + 5]) * s;
            p = qmul(p, dq);
        }
    }
    // normalize partial product (keeps tree combine well-scaled)
    {
        const float n2 = p.w * p.w + p.x * p.x + p.y * p.y + p.z * p.z;
        const float inv = rsqrtf(fmaxf(n2, 1e-24f));
        p.w *= inv; p.x *= inv; p.y *= inv; p.z *= inv;
    }

    // ---- ordered warp tree reduction ----
    #pragma unroll
    for (int off = 1; off < 32; off <<= 1) {
        Quat q;
        q.w = __shfl_down_sync(0xffffffffu, p.w, off);
        q.x = __shfl_down_sync(0xffffffffu, p.x, off);
        q.y = __shfl_down_sync(0xffffffffu, p.y, off);
        q.z = __shfl_down_sync(0xffffffffu, p.z, off);
        if (lane + off < 32) p = qmul(p, q);
    }
    if (lane == 0) s_wq[wid] = make_float4(p.w, p.x, p.y, p.z);
    __syncthreads();

    // ---- warp 0: ordered reduce of 8 warp products, finalize ----
    if (wid == 0) {
        Quat r; r.w = 1.f; r.x = 0.f; r.y = 0.f; r.z = 0.f;
        if (lane < THREADS / 32) {
            float4 v = s_wq[lane];
            r.w = v.x; r.x = v.y; r.y = v.z; r.z = v.w;
        }
        #pragma unroll
        for (int off = 1; off < THREADS / 32; off <<= 1) {
            Quat q;
            q.w = __shfl_down_sync(0xffffffffu, r.w, off);
            q.x = __shfl_down_sync(0xffffffffu, r.x, off);
            q.y = __shfl_down_sync(0xffffffffu, r.y, off);
            q.z = __shfl_down_sync(0xffffffffu, r.z, off);
            if (lane + off < THREADS / 32) r = qmul(r, q);
        }
        if (lane == 0) {
            Quat q0;
            const float* qp = q0g + (size_t)b * 4;
            q0.w = qp[0]; q0.x = qp[1]; q0.y = qp[2]; q0.z = qp[3];
            Quat f = qmul(q0, r);
            const float n = sqrtf(f.w * f.w + f.x * f.x + f.y * f.y + f.z * f.z);
            const float inv = 1.0f / fmaxf(n, 1e-12f);
            float* op = out + (size_t)b * 4;
            op[0] = f.w * inv;
            op[1] = f.x * inv;
            op[2] = f.y * inv;
            op[3] = f.z * inv;
        }
    }
}

extern "C" void kernel_launch(void* const* d_in, const int* in_sizes, int n_in,
                              void* d_out, int out_size) {
    const float* ts   = (const float*)d_in[0];
    const float* gyro = (const float*)d_in[1];
    const float* q0   = (const float*)d_in[2];
    const float* W1   = (const float*)d_in[3];
    const float* b1   = (const float*)d_in[4];
    const float* a1   = (const float*)d_in[5];
    const float* W2   = (const float*)d_in[6];
    const float* b2   = (const float*)d_in[7];
    const float* a2   = (const float*)d_in[8];
    float* out = (float*)d_out;

    const int B   = in_sizes[2] / 4;   // start_quat is (B,4)
    const int CNT = in_sizes[0] / B;   // timestamps are (B,CNT)

    tinygc2l_kernel<<<B, THREADS>>>(ts, gyro, q0, W1, b1, a1, W2, b2, a2, out, CNT);
}